// round 2
// baseline (speedup 1.0000x reference)
#include <cuda_runtime.h>

// C3 sparse-connectivity conv, 5x5 VALID, fp32, f32x2-packed FMA.
// x: [32,6,512,512] f32, weight: [16,6,5,5] f32, bias: [16] f32
// out: [32,16,508,508] f32
//
// Block: 128(w) x 8(h) output tile, all 16 output channels, one batch image.
// 256 threads: warp = output row, lane -> 4 consecutive x pixels.
// Accumulators packed as f32x2 pairs {p0,p1},{p2,p3} -> fma.rn.f32x2.

#define OW 508
#define OH 508
#define IW 512
#define IH 512
#define TILE_W 128
#define TILE_H 8
#define IN_W 132   // TILE_W + 4
#define IN_H 12    // TILE_H + 4

// per-input-channel list of connected output channels (10 each, 60 edges)
__constant__ int d_OC[6][10] = {
    {0, 4, 5, 6, 9, 10, 11, 12, 14, 15},
    {0, 1, 5, 6, 7, 10, 11, 12, 13, 15},
    {0, 1, 2, 6, 7, 8, 11, 13, 14, 15},
    {1, 2, 3, 6, 7, 8, 9, 12, 14, 15},
    {2, 3, 4, 7, 8, 9, 10, 12, 13, 15},
    {3, 4, 5, 8, 9, 10, 11, 13, 14, 15}};

__device__ __forceinline__ unsigned long long pack2(float lo, float hi) {
    unsigned long long r;
    asm("mov.b64 %0, {%1, %2};" : "=l"(r) : "f"(lo), "f"(hi));
    return r;
}
__device__ __forceinline__ void unpack2(unsigned long long v, float& lo, float& hi) {
    asm("mov.b64 {%0, %1}, %2;" : "=f"(lo), "=f"(hi) : "l"(v));
}
// d += a * b (packed fp32 x2) — ptxas only emits FFMA2 from explicit PTX.
__device__ __forceinline__ void ffma2(unsigned long long& d,
                                      unsigned long long a,
                                      unsigned long long b) {
    asm("fma.rn.f32x2 %0, %1, %2, %0;" : "+l"(d) : "l"(a), "l"(b));
}

__global__ void __launch_bounds__(256)
c3_kernel(const float* __restrict__ x,
          const float* __restrict__ wgt,
          const float* __restrict__ bias,
          float* __restrict__ out)
{
    __shared__ float s_in[6][IN_H][IN_W];   // 38016 B
    __shared__ float s_w[6][10][5][8];      //  9600 B (kx padded to 8 -> LDS.128)
    __shared__ float s_b[16];

    const int tid = threadIdx.x;
    const int x0 = blockIdx.x * TILE_W;
    const int y0 = blockIdx.y * TILE_H;
    const int b  = blockIdx.z;

    // ---- load input tile (OOB -> 0; OOB only feeds skipped outputs) ----
    const float* xb = x + (size_t)b * 6 * IH * IW;
    for (int i = tid; i < 6 * IN_H * IN_W; i += 256) {
        int c   = i / (IN_H * IN_W);
        int r   = (i / IN_W) % IN_H;
        int col = i % IN_W;
        int gy = y0 + r, gx = x0 + col;
        float v = 0.0f;
        if (gy < IH && gx < IW) v = __ldg(&xb[(c * IH + gy) * IW + gx]);
        s_in[c][r][col] = v;
    }
    // ---- repack sparse weights ----
    for (int i = tid; i < 1500; i += 256) {
        int ic = i / 250;
        int jj = (i / 25) % 10;
        int k  = i % 25;
        int ky = k / 5, kx = k % 5;
        int oc = d_OC[ic][jj];
        s_w[ic][jj][ky][kx] = __ldg(&wgt[((oc * 6 + ic) * 5 + ky) * 5 + kx]);
    }
    if (tid < 16) s_b[tid] = __ldg(&bias[tid]);
    __syncthreads();

    const int wid  = tid >> 5;       // output row within tile
    const int lane = tid & 31;
    const int lx   = lane * 4;       // output x offset within tile

    // packed accumulators: acc[oc][0] = {p0,p1}, acc[oc][1] = {p2,p3}
    unsigned long long acc[16][2];
#pragma unroll
    for (int oc = 0; oc < 16; ++oc) {
        unsigned long long bv = pack2(s_b[oc], s_b[oc]);
        acc[oc][0] = bv;
        acc[oc][1] = bv;
    }

    constexpr int OC_CT[6][10] = {
        {0, 4, 5, 6, 9, 10, 11, 12, 14, 15},
        {0, 1, 5, 6, 7, 10, 11, 12, 13, 15},
        {0, 1, 2, 6, 7, 8, 11, 13, 14, 15},
        {1, 2, 3, 6, 7, 8, 9, 12, 14, 15},
        {2, 3, 4, 7, 8, 9, 10, 12, 13, 15},
        {3, 4, 5, 8, 9, 10, 11, 13, 14, 15}};

#pragma unroll
    for (int ic = 0; ic < 6; ++ic) {
#pragma unroll 1
        for (int ky = 0; ky < 5; ++ky) {
            // 8-float sliding window for 4 pixels x 5 taps
            const float* rp = &s_in[ic][wid + ky][lx];
            float4 va = *reinterpret_cast<const float4*>(rp);
            float4 vb = *reinterpret_cast<const float4*>(rp + 4);
            float v[8];
            v[0] = va.x; v[1] = va.y; v[2] = va.z; v[3] = va.w;
            v[4] = vb.x; v[5] = vb.y; v[6] = vb.z; v[7] = vb.w;
            // packed windows: P[k] = {v[k], v[k+1]}
            unsigned long long P[7];
#pragma unroll
            for (int k = 0; k < 7; ++k) P[k] = pack2(v[k], v[k + 1]);

#pragma unroll
            for (int j = 0; j < 10; ++j) {
                const int oc = OC_CT[ic][j];
                const float* wp = &s_w[ic][j][ky][0];
                float4 w0 = *reinterpret_cast<const float4*>(wp);
                float wk[5];
                wk[0] = w0.x; wk[1] = w0.y; wk[2] = w0.z; wk[3] = w0.w;
                wk[4] = wp[4];
#pragma unroll
                for (int kx = 0; kx < 5; ++kx) {
                    unsigned long long ws = pack2(wk[kx], wk[kx]);
                    ffma2(acc[oc][0], P[kx],     ws);  // pixels 0,1
                    ffma2(acc[oc][1], P[kx + 2], ws);  // pixels 2,3
                }
            }
        }
    }

    // ---- store: float4 per oc (OW=508 divisible by 4) ----
    const int oy = y0 + wid;
    const int ox = x0 + lx;
    if (oy < OH && ox < OW) {
#pragma unroll
        for (int oc = 0; oc < 16; ++oc) {
            float4 r;
            unpack2(acc[oc][0], r.x, r.y);
            unpack2(acc[oc][1], r.z, r.w);
            *reinterpret_cast<float4*>(
                out + (((size_t)b * 16 + oc) * OH + oy) * OW + ox) = r;
        }
    }
}

extern "C" void kernel_launch(void* const* d_in, const int* in_sizes, int n_in,
                              void* d_out, int out_size)
{
    const float* x    = (const float*)d_in[0];  // [32,6,512,512]
    const float* wgt  = (const float*)d_in[1];  // [16,6,5,5]
    const float* bias = (const float*)d_in[2];  // [16]
    float* out = (float*)d_out;                 // [32,16,508,508]

    dim3 grid((OW + TILE_W - 1) / TILE_W,       // 4
              (OH + TILE_H - 1) / TILE_H,       // 64
              32);                              // batch
    c3_kernel<<<grid, 256>>>(x, wgt, bias, out);
}